// round 1
// baseline (speedup 1.0000x reference)
#include <cuda_runtime.h>

#define M_DIM 8192
#define N_DIM 8192
#define IN_DIM 128
#define HID 256
#define TOPK 512
#define NBINS 4096
#define CAND_CAP (1 << 20)

// ---------------- device scratch (no allocations allowed) ----------------
__device__ float g_md0[M_DIM * HID];
__device__ float g_md1[N_DIM * HID];
__device__ unsigned int g_hist[NBINS];
__device__ unsigned int g_cut;
__device__ unsigned int g_cand_count;
__device__ float g_cand_val[CAND_CAP];
__device__ unsigned int g_cand_idx[CAND_CAP];

// ---------------- reset (graph replays must be deterministic) ----------------
__global__ void reset_kernel() {
    int t = threadIdx.x;
    for (int i = t; i < NBINS; i += blockDim.x) g_hist[i] = 0;
    if (t == 0) g_cand_count = 0;
}

// ---------------- MLP: out = relu(x@Wa + ba) @ Wb + bb ----------------
// Block: 256 threads (one output column each), 32 rows per block. Grid: 256.
__global__ void __launch_bounds__(256) mlp_kernel(
    const float* __restrict__ x,
    const float* __restrict__ Wa, const float* __restrict__ ba,
    const float* __restrict__ Wb, const float* __restrict__ bb,
    int which)  // 0 -> g_md0, 1 -> g_md1
{
    __shared__ float xs[32 * IN_DIM];  // 16 KB
    __shared__ float hs[32 * HID];     // 32 KB
    float* out = (which == 0) ? g_md0 : g_md1;

    int tid = threadIdx.x;           // output column 0..255
    int blk = blockIdx.x;            // 32-row group
    const float* xb = x + (size_t)blk * 32 * IN_DIM;

    for (int i = tid; i < 32 * IN_DIM; i += 256) xs[i] = xb[i];
    __syncthreads();

    float acc[32];
    float bav = ba[tid];
#pragma unroll
    for (int r = 0; r < 32; r++) acc[r] = bav;
    for (int k = 0; k < IN_DIM; k++) {
        float w = Wa[k * HID + tid];  // coalesced across threads
#pragma unroll
        for (int r = 0; r < 32; r++) acc[r] += xs[r * IN_DIM + k] * w;  // broadcast
    }
#pragma unroll
    for (int r = 0; r < 32; r++) hs[r * HID + tid] = fmaxf(acc[r], 0.0f);
    __syncthreads();

    float bbv = bb[tid];
#pragma unroll
    for (int r = 0; r < 32; r++) acc[r] = bbv;
    for (int k = 0; k < HID; k++) {
        float w = Wb[k * HID + tid];
#pragma unroll
        for (int r = 0; r < 32; r++) acc[r] += hs[r * HID + k] * w;
    }
#pragma unroll
    for (int r = 0; r < 32; r++)
        out[((size_t)blk * 32 + r) * HID + tid] = acc[r];
}

// ---------------- NT SGEMM: sim[m][n] = sum_k md0[m][k]*md1[n][k] ----------------
// 128x128 block tile, 256 threads, 8x8 per thread, BK=8. Grid (64, 64).
__global__ void __launch_bounds__(256) gemm_nt_kernel(float* __restrict__ C) {
    __shared__ float As[8][128];
    __shared__ float Bs[8][128];

    int t = threadIdx.x;
    int m0 = blockIdx.y * 128;
    int n0 = blockIdx.x * 128;

    int lrow = t >> 1;          // 0..127
    int lseg = (t & 1) * 4;     // 0 or 4

    int tx = t & 15, ty = t >> 4;
    int tm = ty * 8, tn = tx * 8;

    const float* Abase = g_md0 + (size_t)(m0 + lrow) * HID + lseg;
    const float* Bbase = g_md1 + (size_t)(n0 + lrow) * HID + lseg;

    float acc[8][8];
#pragma unroll
    for (int i = 0; i < 8; i++)
#pragma unroll
        for (int j = 0; j < 8; j++) acc[i][j] = 0.0f;

    for (int kt = 0; kt < HID; kt += 8) {
        float4 va = *(const float4*)(Abase + kt);
        float4 vb = *(const float4*)(Bbase + kt);
        __syncthreads();  // prev compute done before overwrite
        As[lseg + 0][lrow] = va.x; As[lseg + 1][lrow] = va.y;
        As[lseg + 2][lrow] = va.z; As[lseg + 3][lrow] = va.w;
        Bs[lseg + 0][lrow] = vb.x; Bs[lseg + 1][lrow] = vb.y;
        Bs[lseg + 2][lrow] = vb.z; Bs[lseg + 3][lrow] = vb.w;
        __syncthreads();

#pragma unroll
        for (int k = 0; k < 8; k++) {
            float ar[8], br[8];
#pragma unroll
            for (int i = 0; i < 8; i++) ar[i] = As[k][tm + i];
#pragma unroll
            for (int j = 0; j < 8; j++) br[j] = Bs[k][tn + j];
#pragma unroll
            for (int i = 0; i < 8; i++)
#pragma unroll
                for (int j = 0; j < 8; j++) acc[i][j] += ar[i] * br[j];
        }
    }

    // epilogue: float4 stores
#pragma unroll
    for (int i = 0; i < 8; i++) {
        float* cp = C + (size_t)(m0 + tm + i) * N_DIM + (n0 + tn);
        float4 v0 = make_float4(acc[i][0], acc[i][1], acc[i][2], acc[i][3]);
        float4 v1 = make_float4(acc[i][4], acc[i][5], acc[i][6], acc[i][7]);
        *(float4*)(cp + 0) = v0;
        *(float4*)(cp + 4) = v1;
    }
}

// ---------------- top-k: monotone float->uint key ----------------
__device__ __forceinline__ unsigned int fkey(float v) {
    unsigned int u = __float_as_uint(v);
    return (u & 0x80000000u) ? ~u : (u | 0x80000000u);
}

__global__ void hist_kernel(const float4* __restrict__ sim4, int n4) {
    __shared__ unsigned int sh[NBINS];
    for (int i = threadIdx.x; i < NBINS; i += blockDim.x) sh[i] = 0;
    __syncthreads();
    int stride = gridDim.x * blockDim.x;
    for (int i = blockIdx.x * blockDim.x + threadIdx.x; i < n4; i += stride) {
        float4 v = sim4[i];
        atomicAdd(&sh[fkey(v.x) >> 20], 1u);
        atomicAdd(&sh[fkey(v.y) >> 20], 1u);
        atomicAdd(&sh[fkey(v.z) >> 20], 1u);
        atomicAdd(&sh[fkey(v.w) >> 20], 1u);
    }
    __syncthreads();
    for (int i = threadIdx.x; i < NBINS; i += blockDim.x)
        if (sh[i]) atomicAdd(&g_hist[i], sh[i]);
}

__global__ void cut_kernel() {
    if (threadIdx.x == 0) {
        unsigned int c = 0;
        int b = NBINS - 1;
        for (; b > 0; b--) {
            c += g_hist[b];
            if (c >= TOPK) break;
        }
        g_cut = (unsigned int)b;  // candidates: all elements with bin >= b
    }
}

__global__ void cand_kernel(const float4* __restrict__ sim4, int n4) {
    unsigned int cut = g_cut;
    int stride = gridDim.x * blockDim.x;
    for (int i = blockIdx.x * blockDim.x + threadIdx.x; i < n4; i += stride) {
        float4 v = sim4[i];
        float vv[4] = {v.x, v.y, v.z, v.w};
#pragma unroll
        for (int j = 0; j < 4; j++) {
            if ((fkey(vv[j]) >> 20) >= cut) {
                unsigned int pos = atomicAdd(&g_cand_count, 1u);
                if (pos < CAND_CAP) {
                    g_cand_val[pos] = vv[j];
                    g_cand_idx[pos] = (unsigned int)(4 * i + j);
                }
            }
        }
    }
}

// Rank-select: deterministic regardless of candidate append order.
// Tie-break on lower flat index (matches stable lax.top_k).
__global__ void rank_kernel(float* __restrict__ idx_out) {
    unsigned int count = g_cand_count;
    if (count > CAND_CAP) count = CAND_CAP;
    unsigned int stride = gridDim.x * blockDim.x;
    for (unsigned int i = blockIdx.x * blockDim.x + threadIdx.x; i < count; i += stride) {
        float vi = g_cand_val[i];
        unsigned int ii = g_cand_idx[i];
        unsigned int rank = 0;
        for (unsigned int j = 0; j < count; j++) {
            float vj = g_cand_val[j];
            unsigned int ij = g_cand_idx[j];
            if (vj > vi || (vj == vi && ij < ii)) rank++;
        }
        if (rank < TOPK) {
            idx_out[rank * 2 + 0] = (float)(ii >> 13);      // row = idx / 8192
            idx_out[rank * 2 + 1] = (float)(ii & 8191u);    // col = idx % 8192
        }
    }
}

// ---------------- launch ----------------
extern "C" void kernel_launch(void* const* d_in, const int* in_sizes, int n_in,
                              void* d_out, int out_size) {
    const float* desc0 = (const float*)d_in[0];
    const float* desc1 = (const float*)d_in[1];
    const float* W0a = (const float*)d_in[2];
    const float* b0a = (const float*)d_in[3];
    const float* W0b = (const float*)d_in[4];
    const float* b0b = (const float*)d_in[5];
    const float* W1a = (const float*)d_in[6];
    const float* b1a = (const float*)d_in[7];
    const float* W1b = (const float*)d_in[8];
    const float* b1b = (const float*)d_in[9];

    float* out = (float*)d_out;
    long long simN = (long long)M_DIM * N_DIM;
    long long extra = (long long)out_size - simN;

    float* idx_out = nullptr;
    float* sim = out;
    if (extra >= 2 * TOPK) {  // tuple layout: [indices (TOPK*2)] [sim (M*N)]
        idx_out = out;
        sim = out + extra;
    }

    reset_kernel<<<1, 1024>>>();
    mlp_kernel<<<M_DIM / 32, 256>>>(desc0, W0a, b0a, W0b, b0b, 0);
    mlp_kernel<<<N_DIM / 32, 256>>>(desc1, W1a, b1a, W1b, b1b, 1);
    gemm_nt_kernel<<<dim3(N_DIM / 128, M_DIM / 128), 256>>>(sim);

    if (idx_out) {
        int n4 = (int)(simN / 4);
        hist_kernel<<<1184, 256>>>((const float4*)sim, n4);
        cut_kernel<<<1, 32>>>();
        cand_kernel<<<1184, 256>>>((const float4*)sim, n4);
        rank_kernel<<<256, 256>>>(idx_out);
    }
}

// round 5
// speedup vs baseline: 1.8281x; 1.8281x over previous
#include <cuda_runtime.h>
#include <cuda_fp16.h>
#include <cstdint>

#define M_DIM 8192
#define N_DIM 8192
#define IN_DIM 128
#define HID 256
#define TOPK 512
#define WINBINS 512
#define CAND_CAP (1 << 16)

// ---------------- device scratch (no allocations allowed) ----------------
__device__ __half g_md0h[M_DIM * HID];
__device__ __half g_md0l[M_DIM * HID];
__device__ __half g_md1h[N_DIM * HID];
__device__ __half g_md1l[N_DIM * HID];
__device__ float g_md0f[M_DIM * HID];
__device__ float g_md1f[N_DIM * HID];
__device__ unsigned int g_hist[WINBINS];
__device__ unsigned int g_maxkey;
__device__ unsigned int g_cutabs;   // 16-bit key threshold
__device__ unsigned int g_cand_count;
__device__ unsigned int g_cand_idx[CAND_CAP];
__device__ double g_cand_ref[CAND_CAP];

__device__ __forceinline__ unsigned int fkey(float v) {
    unsigned int u = __float_as_uint(v);
    return (u & 0x80000000u) ? ~u : (u | 0x80000000u);
}

// ---------------- reset ----------------
__global__ void reset_kernel() {
    int t = threadIdx.x;
    if (t < WINBINS) g_hist[t] = 0;
    if (t == 0) { g_maxkey = 0; g_cand_count = 0; }
}

// ---------------- MLP -> fp32 plane + fp16 hi/lo planes ----------------
__global__ void __launch_bounds__(256) mlp_kernel(
    const float* __restrict__ x,
    const float* __restrict__ Wa, const float* __restrict__ ba,
    const float* __restrict__ Wb, const float* __restrict__ bb,
    int which)
{
    __shared__ float xs[32 * IN_DIM];
    __shared__ float hs[32 * HID];
    __half* outh = (which == 0) ? g_md0h : g_md1h;
    __half* outl = (which == 0) ? g_md0l : g_md1l;
    float* outf = (which == 0) ? g_md0f : g_md1f;

    int tid = threadIdx.x;
    int blk = blockIdx.x;
    const float* xb = x + (size_t)blk * 32 * IN_DIM;

    {
        const float4* src = (const float4*)xb;
        float4* dst = (float4*)xs;
        for (int i = tid; i < 32 * IN_DIM / 4; i += 256) dst[i] = src[i];
    }
    __syncthreads();

    float acc[32];
    float bav = ba[tid];
#pragma unroll
    for (int r = 0; r < 32; r++) acc[r] = bav;

    const float4* xs4 = (const float4*)xs;
    for (int k = 0; k < IN_DIM; k += 4) {
        float w0 = Wa[(k + 0) * HID + tid];
        float w1 = Wa[(k + 1) * HID + tid];
        float w2 = Wa[(k + 2) * HID + tid];
        float w3 = Wa[(k + 3) * HID + tid];
#pragma unroll
        for (int r = 0; r < 32; r++) {
            float4 xv = xs4[r * (IN_DIM / 4) + (k >> 2)];
            acc[r] += xv.x * w0; acc[r] += xv.y * w1;
            acc[r] += xv.z * w2; acc[r] += xv.w * w3;
        }
    }
#pragma unroll
    for (int r = 0; r < 32; r++) hs[r * HID + tid] = fmaxf(acc[r], 0.0f);
    __syncthreads();

    float bbv = bb[tid];
#pragma unroll
    for (int r = 0; r < 32; r++) acc[r] = bbv;

    const float4* hs4 = (const float4*)hs;
    for (int k = 0; k < HID; k += 4) {
        float w0 = Wb[(k + 0) * HID + tid];
        float w1 = Wb[(k + 1) * HID + tid];
        float w2 = Wb[(k + 2) * HID + tid];
        float w3 = Wb[(k + 3) * HID + tid];
#pragma unroll
        for (int r = 0; r < 32; r++) {
            float4 hv = hs4[r * (HID / 4) + (k >> 2)];
            acc[r] += hv.x * w0; acc[r] += hv.y * w1;
            acc[r] += hv.z * w2; acc[r] += hv.w * w3;
        }
    }
#pragma unroll
    for (int r = 0; r < 32; r++) {
        float v = acc[r];
        __half hi = __float2half_rn(v);
        __half lo = __float2half_rn(v - __half2float(hi));
        size_t o = ((size_t)blk * 32 + r) * HID + tid;
        outh[o] = hi;
        outl[o] = lo;
        outf[o] = v;
    }
}

// ---------------- fp16 3-term NT GEMM via mma.sync (compute_103-safe) ----------------
#define BK 64
#define PITCH 72                       // halves per smem row (144B, conflict-free)
#define PLANE_BYTES (128 * PITCH * 2)  // 18432
#define BUF_BYTES (4 * PLANE_BYTES)    // 73728 (Ah, Al, Bh, Bl)
#define GSMEM_BYTES (2 * BUF_BYTES)    // 147456

__device__ __forceinline__ uint32_t smem_u32(const void* p) {
    uint32_t a;
    asm("{ .reg .u64 t; cvta.to.shared.u64 t, %1; cvt.u32.u64 %0, t; }" : "=r"(a) : "l"(p));
    return a;
}

__device__ __forceinline__ void cp16(uint32_t dst, const void* src) {
    asm volatile("cp.async.cg.shared.global [%0], [%1], 16;" :: "r"(dst), "l"(src) : "memory");
}
__device__ __forceinline__ void cp_commit() { asm volatile("cp.async.commit_group;" ::: "memory"); }
template <int N>
__device__ __forceinline__ void cp_wait() { asm volatile("cp.async.wait_group %0;" :: "n"(N) : "memory"); }

__device__ __forceinline__ void mma16816(float* d, uint32_t a0, uint32_t a1, uint32_t a2,
                                         uint32_t a3, uint32_t b0, uint32_t b1) {
    asm volatile(
        "mma.sync.aligned.m16n8k16.row.col.f32.f16.f16.f32 "
        "{%0,%1,%2,%3}, {%4,%5,%6,%7}, {%8,%9}, {%0,%1,%2,%3};"
        : "+f"(d[0]), "+f"(d[1]), "+f"(d[2]), "+f"(d[3])
        : "r"(a0), "r"(a1), "r"(a2), "r"(a3), "r"(b0), "r"(b1));
}

__global__ void __launch_bounds__(256) gemm_mma_kernel(float* __restrict__ C) {
    extern __shared__ char smem[];
    uint32_t sb = smem_u32(smem);

    int tid = threadIdx.x;
    int wid = tid >> 5;
    int lane = tid & 31;
    int gid = lane >> 2;
    int tig = lane & 3;
    int m0 = blockIdx.y * 128;
    int n0 = blockIdx.x * 128;
    int wm = (wid >> 2) * 64;
    int wn = (wid & 3) * 32;

    float acc[4][4][4];
#pragma unroll
    for (int i = 0; i < 4; i++)
#pragma unroll
        for (int j = 0; j < 4; j++)
#pragma unroll
            for (int k = 0; k < 4; k++) acc[i][j][k] = 0.0f;

    const __half* planes_g[4] = {g_md0h, g_md0l, g_md1h, g_md1l};

    auto issue_chunk = [&](int kc, int buf) {
        uint32_t base = sb + buf * BUF_BYTES;
#pragma unroll
        for (int p = 0; p < 4; p++) {
            const __half* gp = planes_g[p];
            int row0 = (p < 2) ? m0 : n0;
#pragma unroll
            for (int j = 0; j < 4; j++) {
                int chunk = tid * 4 + j;
                int row = chunk >> 3;
                int seg = chunk & 7;
                uint32_t dst = base + p * PLANE_BYTES + row * (PITCH * 2) + seg * 16;
                const void* src = gp + (size_t)(row0 + row) * HID + kc * BK + seg * 8;
                cp16(dst, src);
            }
        }
        cp_commit();
    };

    issue_chunk(0, 0);

    const int NCH = HID / BK;  // 4
    for (int kc = 0; kc < NCH; kc++) {
        int buf = kc & 1;
        if (kc + 1 < NCH) {
            issue_chunk(kc + 1, (kc + 1) & 1);
            cp_wait<1>();
        } else {
            cp_wait<0>();
        }
        __syncthreads();

        const uint32_t* sAh = (const uint32_t*)(smem + buf * BUF_BYTES + 0 * PLANE_BYTES);
        const uint32_t* sAl = (const uint32_t*)(smem + buf * BUF_BYTES + 1 * PLANE_BYTES);
        const uint32_t* sBh = (const uint32_t*)(smem + buf * BUF_BYTES + 2 * PLANE_BYTES);
        const uint32_t* sBl = (const uint32_t*)(smem + buf * BUF_BYTES + 3 * PLANE_BYTES);
        const int PW = PITCH / 2;  // 36

#pragma unroll
        for (int ks = 0; ks < BK / 16; ks++) {
            int kw = ks * 8;
            uint32_t ah[4][4], al[4][4], bh[4][2], bl[4][2];
#pragma unroll
            for (int mt = 0; mt < 4; mt++) {
                int r = wm + mt * 16 + gid;
                int w0 = r * PW + kw + tig;
                int w1 = (r + 8) * PW + kw + tig;
                ah[mt][0] = sAh[w0];     ah[mt][1] = sAh[w1];
                ah[mt][2] = sAh[w0 + 4]; ah[mt][3] = sAh[w1 + 4];
                al[mt][0] = sAl[w0];     al[mt][1] = sAl[w1];
                al[mt][2] = sAl[w0 + 4]; al[mt][3] = sAl[w1 + 4];
            }
#pragma unroll
            for (int nt = 0; nt < 4; nt++) {
                int r = wn + nt * 8 + gid;
                int w0 = r * PW + kw + tig;
                bh[nt][0] = sBh[w0]; bh[nt][1] = sBh[w0 + 4];
                bl[nt][0] = sBl[w0]; bl[nt][1] = sBl[w0 + 4];
            }
#pragma unroll
            for (int mt = 0; mt < 4; mt++)
#pragma unroll
                for (int nt = 0; nt < 4; nt++) {
                    mma16816(acc[mt][nt], ah[mt][0], ah[mt][1], ah[mt][2], ah[mt][3],
                             bh[nt][0], bh[nt][1]);
                    mma16816(acc[mt][nt], ah[mt][0], ah[mt][1], ah[mt][2], ah[mt][3],
                             bl[nt][0], bl[nt][1]);
                    mma16816(acc[mt][nt], al[mt][0], al[mt][1], al[mt][2], al[mt][3],
                             bh[nt][0], bh[nt][1]);
                }
        }
        __syncthreads();
    }

    // epilogue: store C + fused global max
    unsigned int mymax = 0;
#pragma unroll
    for (int mt = 0; mt < 4; mt++) {
        int r0 = m0 + wm + mt * 16 + gid;
#pragma unroll
        for (int nt = 0; nt < 4; nt++) {
            int col = n0 + wn + nt * 8 + 2 * tig;
            float* p0 = C + (size_t)r0 * N_DIM + col;
            float* p1 = C + (size_t)(r0 + 8) * N_DIM + col;
            *(float2*)p0 = make_float2(acc[mt][nt][0], acc[mt][nt][1]);
            *(float2*)p1 = make_float2(acc[mt][nt][2], acc[mt][nt][3]);
            unsigned int k0 = fkey(acc[mt][nt][0]), k1 = fkey(acc[mt][nt][1]);
            unsigned int k2 = fkey(acc[mt][nt][2]), k3 = fkey(acc[mt][nt][3]);
            mymax = max(max(mymax, max(k0, k1)), max(k2, k3));
        }
    }
#pragma unroll
    for (int s = 16; s > 0; s >>= 1)
        mymax = max(mymax, __shfl_xor_sync(0xffffffffu, mymax, s));

    __shared__ unsigned int wmax[8];
    if (lane == 0) wmax[wid] = mymax;
    __syncthreads();
    if (tid == 0) {
        unsigned int m = wmax[0];
#pragma unroll
        for (int i = 1; i < 8; i++) m = max(m, wmax[i]);
        atomicMax(&g_maxkey, m);
    }
}

// ---------------- windowed histogram: only ~4 octaves below max take atomics ----------------
__global__ void hist_kernel(const float4* __restrict__ sim4, int n4) {
    __shared__ unsigned int sh[WINBINS];
    for (int i = threadIdx.x; i < WINBINS; i += blockDim.x) sh[i] = 0;
    __syncthreads();
    unsigned int maxk16 = g_maxkey >> 16;
    int stride = gridDim.x * blockDim.x;
    for (int i = blockIdx.x * blockDim.x + threadIdx.x; i < n4; i += stride) {
        float4 v = sim4[i];
        float vv[4] = {v.x, v.y, v.z, v.w};
#pragma unroll
        for (int j = 0; j < 4; j++) {
            unsigned int rel = maxk16 - (fkey(vv[j]) >> 16);  // 0 = max bin
            if (rel < WINBINS) atomicAdd(&sh[rel], 1u);
        }
    }
    __syncthreads();
    for (int i = threadIdx.x; i < WINBINS; i += blockDim.x)
        if (sh[i]) atomicAdd(&g_hist[i], sh[i]);
}

// ---------------- find cut (16-bit key threshold, +1 bin safety margin) ----------------
__global__ void cut_kernel() {
    if (threadIdx.x == 0) {
        unsigned int c = 0;
        int b = 0;
        for (; b < WINBINS; b++) {
            c += g_hist[b];
            if (c >= TOPK) break;
        }
        if (b >= WINBINS) b = WINBINS - 1;
        b += 1;  // margin bin: absorbs approximation error at the cut boundary
        g_cutabs = (g_maxkey >> 16) - (unsigned int)b;
    }
}

// ---------------- candidate collection ----------------
__global__ void cand_kernel(const float4* __restrict__ sim4, int n4) {
    unsigned int cutabs = g_cutabs;
    int stride = gridDim.x * blockDim.x;
    for (int i = blockIdx.x * blockDim.x + threadIdx.x; i < n4; i += stride) {
        float4 v = sim4[i];
        float vv[4] = {v.x, v.y, v.z, v.w};
#pragma unroll
        for (int j = 0; j < 4; j++) {
            if ((fkey(vv[j]) >> 16) >= cutabs) {
                unsigned int pos = atomicAdd(&g_cand_count, 1u);
                if (pos < CAND_CAP) g_cand_idx[pos] = (unsigned int)(4 * i + j);
            }
        }
    }
}

// ---------------- refine: exact fp64 dot per candidate (warp-per-candidate) ----------------
__global__ void refine_kernel() {
    unsigned int count = g_cand_count;
    if (count > CAND_CAP) count = CAND_CAP;
    unsigned int warp = (blockIdx.x * blockDim.x + threadIdx.x) >> 5;
    unsigned int nwarp = (gridDim.x * blockDim.x) >> 5;
    int lane = threadIdx.x & 31;
    for (unsigned int c = warp; c < count; c += nwarp) {
        unsigned int idx = g_cand_idx[c];
        const float* a = g_md0f + (size_t)(idx >> 13) * HID;
        const float* b = g_md1f + (size_t)(idx & 8191u) * HID;
        double s = 0.0;
#pragma unroll
        for (int k = 0; k < HID / 32; k++)
            s += (double)a[k * 32 + lane] * (double)b[k * 32 + lane];
#pragma unroll
        for (int o = 16; o > 0; o >>= 1)
            s += __shfl_xor_sync(0xffffffffu, s, o);
        if (lane == 0) g_cand_ref[c] = s;
    }
}

// ---------------- rank-select on refined values (deterministic, order-independent) ----------------
__global__ void __launch_bounds__(256) rank_kernel(float* __restrict__ idx_out) {
    unsigned int count = g_cand_count;
    if (count > CAND_CAP) count = CAND_CAP;
    unsigned int stride = gridDim.x * blockDim.x;
    for (unsigned int i = blockIdx.x * blockDim.x + threadIdx.x; i < count; i += stride) {
        double vi = g_cand_ref[i];
        unsigned int ii = g_cand_idx[i];
        unsigned int rank = 0;
        for (unsigned int j = 0; j < count; j++) {
            double vj = g_cand_ref[j];
            unsigned int ij = g_cand_idx[j];
            if (vj > vi || (vj == vi && ij < ii)) rank++;
        }
        if (rank < TOPK) {
            idx_out[rank * 2 + 0] = (float)(ii >> 13);
            idx_out[rank * 2 + 1] = (float)(ii & 8191u);
        }
    }
}

// ---------------- launch ----------------
extern "C" void kernel_launch(void* const* d_in, const int* in_sizes, int n_in,
                              void* d_out, int out_size) {
    const float* desc0 = (const float*)d_in[0];
    const float* desc1 = (const float*)d_in[1];
    const float* W0a = (const float*)d_in[2];
    const float* b0a = (const float*)d_in[3];
    const float* W0b = (const float*)d_in[4];
    const float* b0b = (const float*)d_in[5];
    const float* W1a = (const float*)d_in[6];
    const float* b1a = (const float*)d_in[7];
    const float* W1b = (const float*)d_in[8];
    const float* b1b = (const float*)d_in[9];

    float* out = (float*)d_out;
    long long simN = (long long)M_DIM * N_DIM;
    long long extra = (long long)out_size - simN;

    float* idx_out = nullptr;
    float* sim = out;
    if (extra >= 2 * TOPK) {  // tuple layout: [indices (TOPK*2)] [sim (M*N)]
        idx_out = out;
        sim = out + extra;
    }

    cudaFuncSetAttribute(gemm_mma_kernel,
                         cudaFuncAttributeMaxDynamicSharedMemorySize, GSMEM_BYTES);

    reset_kernel<<<1, 1024>>>();
    mlp_kernel<<<M_DIM / 32, 256>>>(desc0, W0a, b0a, W0b, b0b, 0);
    mlp_kernel<<<N_DIM / 32, 256>>>(desc1, W1a, b1a, W1b, b1b, 1);
    gemm_mma_kernel<<<dim3(N_DIM / 128, M_DIM / 128), 256, GSMEM_BYTES>>>(sim);

    if (idx_out) {
        int n4 = (int)(simN / 4);
        hist_kernel<<<1184, 256>>>((const float4*)sim, n4);
        cut_kernel<<<1, 32>>>();
        cand_kernel<<<1184, 256>>>((const float4*)sim, n4);
        refine_kernel<<<128, 256>>>();
        rank_kernel<<<64, 256>>>(idx_out);
    }
}